// round 10
// baseline (speedup 1.0000x reference)
#include <cuda_runtime.h>
#include <cstdint>

// Patcher: x (8,3,1024,1024) fp32, patch=24, stride=16, reflect pad m=4.
// out[((b*64+ph)*64+pw)*1728 + (i*24+j)*3 + c] = x[b,c,ry,rx]
//   ry=reflect(ph*16+i-4), rx=reflect(pw*16+j-4); reflect: q<0->-q, q>1023->2046-q.
//
// Direct barrier-free kernel: one thread = one output float4 (x2 grid-stride).
// Stores: consecutive threads -> consecutive float4 -> 4 wavefronts/STG (floor).
// Loads: 4 scalar LDG per f4 from planar input (heavily L2-resident).
// No smem, no barriers; MLP = 8 outstanding loads/thread.

static constexpr unsigned HWu = 1024u * 1024u;
static constexpr long long TOTAL_ELEMS = 56623104LL;
static constexpr unsigned TOTAL_F4 = 14155776u;       // TOTAL_ELEMS / 4
static constexpr unsigned HALF_F4 = TOTAL_F4 / 2u;    // 7,077,888
static constexpr unsigned NBLOCKS = HALF_F4 / 256u;   // 27648 exact

__device__ __forceinline__ int reflect_idx(int q) {
    q = (q < 0) ? -q : q;
    q = (q > 1023) ? (2046 - q) : q;
    return q;
}

__device__ __forceinline__ float4 gather_f4(const float* __restrict__ x,
                                            unsigned idx) {
    // idx -> (b, ph, pw, i, off)
    unsigned patch = idx / 432u;
    unsigned rem   = idx - patch * 432u;
    unsigned i     = rem / 18u;
    unsigned off   = rem - i * 18u;
    unsigned pw  = patch & 63u;
    unsigned phb = patch >> 6;
    unsigned ph  = phb & 63u;
    unsigned b   = phb >> 6;

    int y = reflect_idx((int)(ph << 4) + (int)i - 4);

    unsigned e0 = off << 2;        // element index within row = j*3 + c
    unsigned j  = e0 / 3u;
    unsigned c0 = e0 - j * 3u;

    int xq = (int)(pw << 4) + (int)j - 4;
    int x0 = reflect_idx(xq);
    int x1 = reflect_idx(xq + 1);

    const float* base = x + (size_t)b * (3u * HWu) + ((unsigned)y << 10);

    float v[4];
    #pragma unroll
    for (unsigned k = 0; k < 4; ++k) {
        unsigned cc = c0 + k;
        bool adv = cc >= 3u;
        cc = adv ? cc - 3u : cc;
        int xx = adv ? x1 : x0;
        v[k] = __ldg(base + (cc << 20) + (unsigned)xx);
    }
    float4 o; o.x = v[0]; o.y = v[1]; o.z = v[2]; o.w = v[3];
    return o;
}

__global__ void __launch_bounds__(256)
patcher_kernel(const float* __restrict__ x, float* __restrict__ out,
               unsigned out_size) {
    unsigned g = blockIdx.x * 256u + threadIdx.x;

    if (g < 32u) {   // tail fill: flattened (nH,nW)=(64,64) appended
        unsigned idx = (unsigned)TOTAL_ELEMS + g;
        if (idx < out_size) out[idx] = 64.0f;
    }

    float4* o4 = reinterpret_cast<float4*>(out);

    // Two independent f4s per thread -> 8 loads in flight, stores coalesced.
    float4 r0 = gather_f4(x, g);
    float4 r1 = gather_f4(x, g + HALF_F4);
    o4[g] = r0;
    o4[g + HALF_F4] = r1;
}

extern "C" void kernel_launch(void* const* d_in, const int* in_sizes, int n_in,
                              void* d_out, int out_size) {
    const float* x = (const float*)d_in[0];
    float* out = (float*)d_out;
    patcher_kernel<<<NBLOCKS, 256>>>(x, out, (unsigned)out_size);
}